// round 13
// baseline (speedup 1.0000x reference)
#include <cuda_runtime.h>
#include <cuda_fp16.h>
#include <cstdint>

#define ROWS 32768
#define FDIM 512
#define HDIM 2048

// GEMM tiling: CTA 128x128, 512 threads (16 warps, 4Mx4N, warp tile 32x32),
// BK=32, 4-stage cp.async pipeline.  (R7/R9/R12 config — best measured.)
#define BK 32
#define NSTAGE 4
#define LDSW 40                          // halves per smem row (80B)
#define STAGE_HALVES (128 * LDSW)
#define SMEM_TOTAL (2 * NSTAGE * STAGE_HALVES * 2)   // 81920 B

// ---------------- scratch (device globals; allocation-free) ----------------
__device__ float          g_xs32[(size_t)ROWS * FDIM];
__device__ __half         g_xs16[(size_t)ROWS * FDIM];
__device__ unsigned short g_inv [(size_t)ROWS * FDIM];
__device__ __half         g_h16 [(size_t)ROWS * HDIM];
__device__ __half         g_w1h [(size_t)HDIM * FDIM];
__device__ __half         g_w2h [(size_t)FDIM * HDIM];

// ---------------------------------------------------------------------------
__global__ void cvt_weights(const float* __restrict__ W1, const float* __restrict__ W2) {
    const int QW = (HDIM * FDIM) / 4;
    int i = blockIdx.x * 256 + threadIdx.x;
    const float4* s; __half2* d; int j;
    if (i < QW) { s = (const float4*)W1; d = (__half2*)g_w1h; j = i; }
    else        { s = (const float4*)W2; d = (__half2*)g_w2h; j = i - QW; }
    float4 v = s[j];
    d[2 * j]     = __floats2half2_rn(v.x, v.y);
    d[2 * j + 1] = __floats2half2_rn(v.z, v.w);
}

// ---------------------------------------------------------------------------
// Sort: per-row stable bitonic, ONE WARP per row, 16 keys/thread in registers.
// 8 rows per 256-thread block. Warp-synchronous in the network.
// key = ordered(float)<<32 | index. Reference-exact epilogue:
//   inv[srt[pos]] = pos;  xs[i] = x[inv[i]]
// R13: all GLOBAL loads/stores fully coalesced (staged via smem); the
// network's 64B-strided element ownership only ever touches smem.
// ---------------------------------------------------------------------------
__device__ __forceinline__ void cmpswap(unsigned long long& a, unsigned long long& b,
                                        bool asc) {
    bool sw = asc ? (a > b) : (a < b);
    if (sw) { unsigned long long t = a; a = b; b = t; }
}

__global__ __launch_bounds__(256)
void sort_kernel(const float* __restrict__ x) {
    __shared__ float          xsh[8][FDIM];    // 16 KB raw values
    __shared__ unsigned short invsh[8][FDIM];  //  8 KB inverse perm

    const int sub  = threadIdx.x >> 5;    // row within block (0..7)
    const int lane = threadIdx.x & 31;
    const int row  = blockIdx.x * 8 + sub;
    const int e0   = lane * 16;           // first network element held

    // ---- coalesced load: lane-consecutive float4, stage to smem ----
    const float4* xr = reinterpret_cast<const float4*>(x + (size_t)row * FDIM);
#pragma unroll
    for (int q = 0; q < 4; q++) {
        float4 v = xr[q * 32 + lane];                        // coalesced LDG.128
        *reinterpret_cast<float4*>(&xsh[sub][(q * 32 + lane) * 4]) = v;  // STS.128, conflict-free
    }
    __syncwarp();

    // ---- pull this thread's 16 network elements from smem, build keys ----
    unsigned long long k[16];
#pragma unroll
    for (int g = 0; g < 4; g++) {
        float4 v = *reinterpret_cast<const float4*>(&xsh[sub][e0 + 4 * g]);
        float vv[4] = {v.x, v.y, v.z, v.w};
#pragma unroll
        for (int s2 = 0; s2 < 4; s2++) {
            int s = 4 * g + s2;
            unsigned u = __float_as_uint(vv[s2]);
            u = (u & 0x80000000u) ? ~u : (u | 0x80000000u);
            k[s] = ((unsigned long long)u << 32) | (unsigned)(e0 + s);
        }
    }

    // Phase 1: kk = 2, 4, 8 — purely in-thread, directions compile-time
#pragma unroll
    for (int kk = 2; kk <= 8; kk <<= 1) {
#pragma unroll
        for (int j = kk >> 1; j >= 1; j >>= 1) {
#pragma unroll
            for (int s = 0; s < 16; s++) {
                if ((s & j) == 0) {
                    bool asc = ((s & kk) == 0);      // e0&kk == 0 for kk<=8
                    cmpswap(k[s], k[s | j], asc);
                }
            }
        }
    }

    // Phase 2: kk = 16..512 — uniform direction per thread
#pragma unroll
    for (int kk = 16; kk <= FDIM; kk <<= 1) {
        const bool asc = ((e0 & kk) == 0);
        // cross-lane levels (j >= 16)
#pragma unroll
        for (int j = kk >> 1; j >= 16; j >>= 1) {
            int d = j >> 4;
            bool takeMin = (((lane & d) == 0) == asc);
#pragma unroll
            for (int s = 0; s < 16; s++) {
                unsigned long long o = __shfl_xor_sync(0xffffffffu, k[s], d);
                bool mine = takeMin ? (k[s] <= o) : (k[s] >= o);
                k[s] = mine ? k[s] : o;
            }
        }
        // in-thread levels (j = 8,4,2,1), uniform asc
#pragma unroll
        for (int j = 8; j >= 1; j >>= 1) {
#pragma unroll
            for (int s = 0; s < 16; s++) {
                if ((s & j) == 0)
                    cmpswap(k[s], k[s | j], asc);
            }
        }
    }

    // inv[srt[pos]] = pos  (scatter within this row's smem)
#pragma unroll
    for (int s = 0; s < 16; s++)
        invsh[sub][(unsigned)(k[s] & 0xFFFFFFFFu)] = (unsigned short)(e0 + s);
    __syncwarp();

    // ---- coalesced output: thread owns elements rep*128 + lane*4 ----
    size_t rbase = (size_t)row * FDIM;
#pragma unroll
    for (int rep = 0; rep < 4; rep++) {
        int eb = rep * 128 + lane * 4;
        ushort4 ivv = *reinterpret_cast<const ushort4*>(&invsh[sub][eb]);  // LDS.64, conflict-free
        float a0 = xsh[sub][ivv.x], a1 = xsh[sub][ivv.y];                  // random LDS gather
        float a2 = xsh[sub][ivv.z], a3 = xsh[sub][ivv.w];
        *reinterpret_cast<float4*>(&g_xs32[rbase + eb]) =
            make_float4(a0, a1, a2, a3);                                   // coalesced STG.128
        __half2 hlo = __floats2half2_rn(a0, a1);
        __half2 hhi = __floats2half2_rn(a2, a3);
        uint2 hv = make_uint2(*reinterpret_cast<unsigned*>(&hlo),
                              *reinterpret_cast<unsigned*>(&hhi));
        *reinterpret_cast<uint2*>(&g_xs16[rbase + eb]) = hv;               // coalesced STG.64
        *reinterpret_cast<ushort4*>(&g_inv[rbase + eb]) = ivv;             // coalesced STG.64
    }
}

// ---------------------------------------------------------------------------
// fp16 mma.sync GEMM, 512 threads, warp tile 32x32, 4-stage cp.async pipe.
// A: [M][K] f16 row-major, B: [N][K] f16 row-major.  (R12 config, unchanged.)
// ---------------------------------------------------------------------------
__device__ __forceinline__ void mma16816(float (&c)[4], unsigned a0, unsigned a1,
                                         unsigned a2, unsigned a3,
                                         unsigned b0, unsigned b1) {
    asm volatile(
        "mma.sync.aligned.m16n8k16.row.col.f32.f16.f16.f32 "
        "{%0,%1,%2,%3}, {%4,%5,%6,%7}, {%8,%9}, {%0,%1,%2,%3};"
        : "+f"(c[0]), "+f"(c[1]), "+f"(c[2]), "+f"(c[3])
        : "r"(a0), "r"(a1), "r"(a2), "r"(a3), "r"(b0), "r"(b1));
}

__device__ __forceinline__ void cp16(uint32_t dst, const __half* src) {
    asm volatile("cp.async.cg.shared.global [%0], [%1], 16;"
                 :: "r"(dst), "l"(__cvta_generic_to_global(src)));
}
#define CP_COMMIT() asm volatile("cp.async.commit_group;" ::: "memory")
#define CP_WAIT2()  asm volatile("cp.async.wait_group 2;" ::: "memory")
#define CP_WAIT0()  asm volatile("cp.async.wait_group 0;" ::: "memory")

template <int K>
__device__ __forceinline__ void load_chunk(uint32_t sA, uint32_t sB,
                                           const __half* __restrict__ A,
                                           const __half* __restrict__ B,
                                           int blockM, int blockN, int kt, int tid) {
    int r = tid >> 2;
    int c = (tid & 3) * 8;
    uint32_t so = (uint32_t)(r * LDSW + c) * 2;
    cp16(sA + so, A + (size_t)(blockM + r) * K + kt + c);
    cp16(sB + so, B + (size_t)(blockN + r) * K + kt + c);
}

template <int K>
__device__ __forceinline__ void gemm_body(
    const __half* __restrict__ A, const __half* __restrict__ B,
    float (&acc)[2][4][4], char* smem) {

    const uint32_t smem_base = (uint32_t)__cvta_generic_to_shared(smem);
    const int tid    = threadIdx.x;
    const int lane   = tid & 31;
    const int warp   = tid >> 5;
    const int warp_m = warp >> 2;
    const int warp_n = warp & 3;
    const int blockM = blockIdx.y * 128;
    const int blockN = blockIdx.x * 128;
    constexpr int NK = K / BK;

    const uint32_t A0 = smem_base;
    const uint32_t B0 = smem_base + NSTAGE * STAGE_HALVES * 2;

    const int a_row = warp_m * 32 + (lane & 15);
    const int b_row = warp_n * 32 + (lane & 15);
    const int kof   = (lane >> 4) << 3;

#pragma unroll
    for (int p = 0; p < NSTAGE - 1; p++) {
        load_chunk<K>(A0 + p * STAGE_HALVES * 2, B0 + p * STAGE_HALVES * 2,
                      A, B, blockM, blockN, p * BK, tid);
        CP_COMMIT();
    }

#pragma unroll 1
    for (int kc = 0; kc < NK; kc++) {
        const int stage = kc & (NSTAGE - 1);
        CP_WAIT2();
        __syncthreads();

        const int nf = kc + NSTAGE - 1;
        if (nf < NK) {
            const int ns = nf & (NSTAGE - 1);
            load_chunk<K>(A0 + ns * STAGE_HALVES * 2, B0 + ns * STAGE_HALVES * 2,
                          A, B, blockM, blockN, nf * BK, tid);
        }
        CP_COMMIT();

        const uint32_t sA = A0 + stage * STAGE_HALVES * 2;
        const uint32_t sB = B0 + stage * STAGE_HALVES * 2;
#pragma unroll
        for (int kk = 0; kk < BK; kk += 16) {
            unsigned a[2][4], b[2][4];
#pragma unroll
            for (int mf = 0; mf < 2; mf++) {
                uint32_t addr = sA + ((a_row + mf * 16) * LDSW + kk + kof) * 2;
                asm volatile(
                    "ldmatrix.sync.aligned.m8n8.x4.shared.b16 {%0,%1,%2,%3}, [%4];"
                    : "=r"(a[mf][0]), "=r"(a[mf][1]), "=r"(a[mf][2]), "=r"(a[mf][3])
                    : "r"(addr));
            }
#pragma unroll
            for (int g = 0; g < 2; g++) {
                uint32_t addr = sB + ((b_row + g * 16) * LDSW + kk + kof) * 2;
                asm volatile(
                    "ldmatrix.sync.aligned.m8n8.x4.shared.b16 {%0,%1,%2,%3}, [%4];"
                    : "=r"(b[g][0]), "=r"(b[g][1]), "=r"(b[g][2]), "=r"(b[g][3])
                    : "r"(addr));
            }
#pragma unroll
            for (int mf = 0; mf < 2; mf++)
#pragma unroll
                for (int nn = 0; nn < 4; nn++)
                    mma16816(acc[mf][nn], a[mf][0], a[mf][1], a[mf][2], a[mf][3],
                             b[nn >> 1][nn & 1], b[nn >> 1][(nn & 1) + 2]);
        }
    }
    CP_WAIT0();
}

// GEMM1: h = relu(xs @ W1^T + b1) -> fp16
__global__ __launch_bounds__(512, 2)
void gemm1_kernel(const float* __restrict__ b1) {
    extern __shared__ char smem[];
    float acc[2][4][4] = {};
    gemm_body<FDIM>(g_xs16, g_w1h, acc, smem);

    const int tid  = threadIdx.x;
    const int lane = tid & 31;
    const int warp = tid >> 5;
    const int warp_m = warp >> 2, warp_n = warp & 3;
    const int blockM = blockIdx.y * 128;
    const int blockN = blockIdx.x * 128;

#pragma unroll
    for (int mf = 0; mf < 2; mf++)
#pragma unroll
        for (int nn = 0; nn < 4; nn++) {
            int row = blockM + warp_m * 32 + mf * 16 + (lane >> 2);
            int col = blockN + warp_n * 32 + nn * 8 + (lane & 3) * 2;
            float bb0 = b1[col], bb1 = b1[col + 1];
            __half2 h0 = __floats2half2_rn(fmaxf(acc[mf][nn][0] + bb0, 0.f),
                                           fmaxf(acc[mf][nn][1] + bb1, 0.f));
            __half2 h1 = __floats2half2_rn(fmaxf(acc[mf][nn][2] + bb0, 0.f),
                                           fmaxf(acc[mf][nn][3] + bb1, 0.f));
            *reinterpret_cast<__half2*>(&g_h16[(size_t)row * HDIM + col])       = h0;
            *reinterpret_cast<__half2*>(&g_h16[(size_t)(row + 8) * HDIM + col]) = h1;
        }
}

// GEMM2: y = h @ W2^T + b2 + xs; out[m][inv[n]] = y[m][n]
__global__ __launch_bounds__(512, 2)
void gemm2_kernel(const float* __restrict__ b2, float* __restrict__ out) {
    extern __shared__ char smem[];
    float acc[2][4][4] = {};
    gemm_body<HDIM>(g_h16, g_w2h, acc, smem);

    const int tid  = threadIdx.x;
    const int lane = tid & 31;
    const int warp = tid >> 5;
    const int warp_m = warp >> 2, warp_n = warp & 3;
    const int blockM = blockIdx.y * 128;
    const int blockN = blockIdx.x * 128;

#pragma unroll
    for (int mf = 0; mf < 2; mf++)
#pragma unroll
        for (int nn = 0; nn < 4; nn++) {
            int row = blockM + warp_m * 32 + mf * 16 + (lane >> 2);
            int col = blockN + warp_n * 32 + nn * 8 + (lane & 3) * 2;
            float bb0 = b2[col], bb1 = b2[col + 1];
#pragma unroll
            for (int half = 0; half < 2; half++) {
                int r = row + half * 8;
                size_t base = (size_t)r * FDIM + col;
                float2 xsv = *reinterpret_cast<const float2*>(&g_xs32[base]);
                ushort2 pv = *reinterpret_cast<const ushort2*>(&g_inv[base]);
                float y0 = acc[mf][nn][half * 2 + 0] + bb0 + xsv.x;
                float y1 = acc[mf][nn][half * 2 + 1] + bb1 + xsv.y;
                out[(size_t)r * FDIM + pv.x] = y0;
                out[(size_t)r * FDIM + pv.y] = y1;
            }
        }
}

// ---------------------------------------------------------------------------
// Launch: sequential (overlap regressed twice — all kernels compute-bound,
// SM-seconds conserved under overlap).
// ---------------------------------------------------------------------------
extern "C" void kernel_launch(void* const* d_in, const int* in_sizes, int n_in,
                              void* d_out, int out_size) {
    const float* x  = (const float*)d_in[0];
    const float* W1 = (const float*)d_in[1];
    const float* b1 = (const float*)d_in[2];
    const float* W2 = (const float*)d_in[3];
    const float* b2 = (const float*)d_in[4];
    float* out = (float*)d_out;

    cudaFuncSetAttribute(gemm1_kernel, cudaFuncAttributeMaxDynamicSharedMemorySize, SMEM_TOTAL);
    cudaFuncSetAttribute(gemm2_kernel, cudaFuncAttributeMaxDynamicSharedMemorySize, SMEM_TOTAL);

    cvt_weights<<<(2 * HDIM * FDIM / 4) / 256, 256>>>(W1, W2);
    sort_kernel<<<ROWS / 8, 256>>>(x);
    gemm1_kernel<<<dim3(HDIM / 128, ROWS / 128), 512, SMEM_TOTAL>>>(b1);
    gemm2_kernel<<<dim3(FDIM / 128, ROWS / 128), 512, SMEM_TOTAL>>>(b2, out);
}

// round 16
// speedup vs baseline: 1.3390x; 1.3390x over previous
#include <cuda_runtime.h>
#include <cuda_fp16.h>
#include <cstdint>

#define ROWS 32768
#define FDIM 512
#define HDIM 2048

// GEMM tiling: CTA 128x128, 512 threads (16 warps, 4Mx4N, warp tile 32x32),
// BK=32, 4-stage cp.async pipeline.  (R7/R9/R12 config — best measured.)
#define BK 32
#define NSTAGE 4
#define LDSW 40                          // halves per smem row (80B)
#define STAGE_HALVES (128 * LDSW)
#define SMEM_TOTAL (2 * NSTAGE * STAGE_HALVES * 2)   // 81920 B

// ---------------- scratch (device globals; allocation-free) ----------------
__device__ float          g_xs32[(size_t)ROWS * FDIM];
__device__ __half         g_xs16[(size_t)ROWS * FDIM];
__device__ unsigned short g_inv [(size_t)ROWS * FDIM];
__device__ __half         g_h16 [(size_t)ROWS * HDIM];
__device__ __half         g_w1h [(size_t)HDIM * FDIM];
__device__ __half         g_w2h [(size_t)FDIM * HDIM];

// ---------------------------------------------------------------------------
__global__ void cvt_weights(const float* __restrict__ W1, const float* __restrict__ W2) {
    const int QW = (HDIM * FDIM) / 4;
    int i = blockIdx.x * 256 + threadIdx.x;
    const float4* s; __half2* d; int j;
    if (i < QW) { s = (const float4*)W1; d = (__half2*)g_w1h; j = i; }
    else        { s = (const float4*)W2; d = (__half2*)g_w2h; j = i - QW; }
    float4 v = s[j];
    d[2 * j]     = __floats2half2_rn(v.x, v.y);
    d[2 * j + 1] = __floats2half2_rn(v.z, v.w);
}

// ---------------------------------------------------------------------------
// Sort, two stages, ONE WARP per row, 16 keys/thread, EXACT stable order:
//  Stage 1: bitonic sort of full 32-bit ordered-float keys (value only, no
//           payload — comparator networks sort multisets). Every exchange is
//           IMNMX; all shuffles convergent. Sorted keys -> smem.
//  Stage 2: inv[i] = lower_bound(sorted, key_i) + (stable rank among exact
//           bit-duplicates, rare path). This equals the reference's stable
//           argsort inverse EXACTLY. xs[i] = xsh[inv[i]] (exact values).
// ---------------------------------------------------------------------------
__global__ __launch_bounds__(256)
void sort_kernel(const float* __restrict__ x) {
    __shared__ float    xsh [8][FDIM];    // 16 KB raw values
    __shared__ unsigned skey[8][FDIM];    // 16 KB sorted keys

    const int sub  = threadIdx.x >> 5;    // row within block (0..7)
    const int lane = threadIdx.x & 31;
    const int row  = blockIdx.x * 8 + sub;
    const int e0   = lane * 16;           // first network element held

    // ---- coalesced load, stage raw values to smem ----
    const float4* xr = reinterpret_cast<const float4*>(x + (size_t)row * FDIM);
#pragma unroll
    for (int q = 0; q < 4; q++) {
        float4 v = xr[q * 32 + lane];
        *reinterpret_cast<float4*>(&xsh[sub][(q * 32 + lane) * 4]) = v;
    }
    __syncwarp();

    // ---- build full 32-bit keys for this thread's 16 network elements ----
    unsigned k[16];
#pragma unroll
    for (int g = 0; g < 4; g++) {
        float4 v = *reinterpret_cast<const float4*>(&xsh[sub][e0 + 4 * g]);
        float vv[4] = {v.x, v.y, v.z, v.w};
#pragma unroll
        for (int s2 = 0; s2 < 4; s2++) {
            unsigned u = __float_as_uint(vv[s2]);
            k[4 * g + s2] = (u & 0x80000000u) ? ~u : (u | 0x80000000u);
        }
    }

    // ---- Stage 1: bitonic sort (values only) ----
    // Phase 1: kk = 2, 4, 8 — in-thread, directions compile-time
#pragma unroll
    for (int kk = 2; kk <= 8; kk <<= 1) {
#pragma unroll
        for (int j = kk >> 1; j >= 1; j >>= 1) {
#pragma unroll
            for (int s = 0; s < 16; s++) {
                if ((s & j) == 0) {
                    int p = s | j;
                    unsigned lo = umin(k[s], k[p]), hi = umax(k[s], k[p]);
                    if ((s & kk) == 0) { k[s] = lo; k[p] = hi; }
                    else               { k[s] = hi; k[p] = lo; }
                }
            }
        }
    }
    // Phase 2: kk = 16..512 — direction uniform per thread
#pragma unroll
    for (int kk = 16; kk <= FDIM; kk <<= 1) {
        const bool asc = ((e0 & kk) == 0);
#pragma unroll
        for (int j = kk >> 1; j >= 16; j >>= 1) {
            int d = j >> 4;
            unsigned o[16];
#pragma unroll
            for (int s = 0; s < 16; s++)
                o[s] = __shfl_xor_sync(0xffffffffu, k[s], d);   // convergent
            bool takeMin = (((lane & d) == 0) == asc);
            if (takeMin) {
#pragma unroll
                for (int s = 0; s < 16; s++) k[s] = umin(k[s], o[s]);
            } else {
#pragma unroll
                for (int s = 0; s < 16; s++) k[s] = umax(k[s], o[s]);
            }
        }
        if (asc) {
#pragma unroll
            for (int j = 8; j >= 1; j >>= 1)
#pragma unroll
                for (int s = 0; s < 16; s++)
                    if ((s & j) == 0) {
                        int p = s | j;
                        unsigned lo = umin(k[s], k[p]), hi = umax(k[s], k[p]);
                        k[s] = lo; k[p] = hi;
                    }
        } else {
#pragma unroll
            for (int j = 8; j >= 1; j >>= 1)
#pragma unroll
                for (int s = 0; s < 16; s++)
                    if ((s & j) == 0) {
                        int p = s | j;
                        unsigned lo = umin(k[s], k[p]), hi = umax(k[s], k[p]);
                        k[s] = hi; k[p] = lo;
                    }
        }
    }

    // sorted keys -> smem (k[s] = sorted value at position e0+s)
#pragma unroll
    for (int g = 0; g < 4; g++) {
        uint4 kv = make_uint4(k[4 * g], k[4 * g + 1], k[4 * g + 2], k[4 * g + 3]);
        *reinterpret_cast<uint4*>(&skey[sub][e0 + 4 * g]) = kv;
    }
    __syncwarp();

    // ---- Stage 2: exact inverse permutation via lower_bound + stable rank ----
    size_t rbase = (size_t)row * FDIM;
#pragma unroll
    for (int rep = 0; rep < 4; rep++) {
        int eb = rep * 128 + lane * 4;                 // coalesced ownership
        float4 xv = *reinterpret_cast<const float4*>(&xsh[sub][eb]);
        float raw[4] = {xv.x, xv.y, xv.z, xv.w};
        int   pos[4];
        float xsv[4];
#pragma unroll
        for (int t = 0; t < 4; t++) {
            unsigned u = __float_as_uint(raw[t]);
            unsigned key = (u & 0x80000000u) ? ~u : (u | 0x80000000u);
            // branchless lower_bound over 512 (pos+w-1 <= 511 invariant)
            int p = 0;
#pragma unroll
            for (int w = 256; w >= 1; w >>= 1)
                if (skey[sub][p + w - 1] < key) p += w;
            // rare: exact bit-duplicates -> stable rank by original index
            if (p + 1 < FDIM && skey[sub][p + 1] == key) {
                int i = eb + t;
                int rank = 0;
                for (int jj = 0; jj < i; jj++)
                    rank += (__float_as_uint(xsh[sub][jj]) == u);
                p += rank;
            }
            pos[t] = p;
            xsv[t] = xsh[sub][p];                      // xs[i] = x[inv[i]]
        }
        *reinterpret_cast<float4*>(&g_xs32[rbase + eb]) =
            make_float4(xsv[0], xsv[1], xsv[2], xsv[3]);
        __half2 hlo = __floats2half2_rn(xsv[0], xsv[1]);
        __half2 hhi = __floats2half2_rn(xsv[2], xsv[3]);
        uint2 hv = make_uint2(*reinterpret_cast<unsigned*>(&hlo),
                              *reinterpret_cast<unsigned*>(&hhi));
        *reinterpret_cast<uint2*>(&g_xs16[rbase + eb]) = hv;
        ushort4 iv = make_ushort4((unsigned short)pos[0], (unsigned short)pos[1],
                                  (unsigned short)pos[2], (unsigned short)pos[3]);
        *reinterpret_cast<ushort4*>(&g_inv[rbase + eb]) = iv;
    }
}

// ---------------------------------------------------------------------------
// fp16 mma.sync GEMM, 512 threads, warp tile 32x32, 4-stage cp.async pipe.
// A: [M][K] f16 row-major, B: [N][K] f16 row-major.  (R12 config, unchanged.)
// ---------------------------------------------------------------------------
__device__ __forceinline__ void mma16816(float (&c)[4], unsigned a0, unsigned a1,
                                         unsigned a2, unsigned a3,
                                         unsigned b0, unsigned b1) {
    asm volatile(
        "mma.sync.aligned.m16n8k16.row.col.f32.f16.f16.f32 "
        "{%0,%1,%2,%3}, {%4,%5,%6,%7}, {%8,%9}, {%0,%1,%2,%3};"
        : "+f"(c[0]), "+f"(c[1]), "+f"(c[2]), "+f"(c[3])
        : "r"(a0), "r"(a1), "r"(a2), "r"(a3), "r"(b0), "r"(b1));
}

__device__ __forceinline__ void cp16(uint32_t dst, const __half* src) {
    asm volatile("cp.async.cg.shared.global [%0], [%1], 16;"
                 :: "r"(dst), "l"(__cvta_generic_to_global(src)));
}
#define CP_COMMIT() asm volatile("cp.async.commit_group;" ::: "memory")
#define CP_WAIT2()  asm volatile("cp.async.wait_group 2;" ::: "memory")
#define CP_WAIT0()  asm volatile("cp.async.wait_group 0;" ::: "memory")

template <int K>
__device__ __forceinline__ void load_chunk(uint32_t sA, uint32_t sB,
                                           const __half* __restrict__ A,
                                           const __half* __restrict__ B,
                                           int blockM, int blockN, int kt, int tid) {
    int r = tid >> 2;
    int c = (tid & 3) * 8;
    uint32_t so = (uint32_t)(r * LDSW + c) * 2;
    cp16(sA + so, A + (size_t)(blockM + r) * K + kt + c);
    cp16(sB + so, B + (size_t)(blockN + r) * K + kt + c);
}

template <int K>
__device__ __forceinline__ void gemm_body(
    const __half* __restrict__ A, const __half* __restrict__ B,
    float (&acc)[2][4][4], char* smem) {

    const uint32_t smem_base = (uint32_t)__cvta_generic_to_shared(smem);
    const int tid    = threadIdx.x;
    const int lane   = tid & 31;
    const int warp   = tid >> 5;
    const int warp_m = warp >> 2;
    const int warp_n = warp & 3;
    const int blockM = blockIdx.y * 128;
    const int blockN = blockIdx.x * 128;
    constexpr int NK = K / BK;

    const uint32_t A0 = smem_base;
    const uint32_t B0 = smem_base + NSTAGE * STAGE_HALVES * 2;

    const int a_row = warp_m * 32 + (lane & 15);
    const int b_row = warp_n * 32 + (lane & 15);
    const int kof   = (lane >> 4) << 3;

#pragma unroll
    for (int p = 0; p < NSTAGE - 1; p++) {
        load_chunk<K>(A0 + p * STAGE_HALVES * 2, B0 + p * STAGE_HALVES * 2,
                      A, B, blockM, blockN, p * BK, tid);
        CP_COMMIT();
    }

#pragma unroll 1
    for (int kc = 0; kc < NK; kc++) {
        const int stage = kc & (NSTAGE - 1);
        CP_WAIT2();
        __syncthreads();

        const int nf = kc + NSTAGE - 1;
        if (nf < NK) {
            const int ns = nf & (NSTAGE - 1);
            load_chunk<K>(A0 + ns * STAGE_HALVES * 2, B0 + ns * STAGE_HALVES * 2,
                          A, B, blockM, blockN, nf * BK, tid);
        }
        CP_COMMIT();

        const uint32_t sA = A0 + stage * STAGE_HALVES * 2;
        const uint32_t sB = B0 + stage * STAGE_HALVES * 2;
#pragma unroll
        for (int kk = 0; kk < BK; kk += 16) {
            unsigned a[2][4], b[2][4];
#pragma unroll
            for (int mf = 0; mf < 2; mf++) {
                uint32_t addr = sA + ((a_row + mf * 16) * LDSW + kk + kof) * 2;
                asm volatile(
                    "ldmatrix.sync.aligned.m8n8.x4.shared.b16 {%0,%1,%2,%3}, [%4];"
                    : "=r"(a[mf][0]), "=r"(a[mf][1]), "=r"(a[mf][2]), "=r"(a[mf][3])
                    : "r"(addr));
            }
#pragma unroll
            for (int g = 0; g < 2; g++) {
                uint32_t addr = sB + ((b_row + g * 16) * LDSW + kk + kof) * 2;
                asm volatile(
                    "ldmatrix.sync.aligned.m8n8.x4.shared.b16 {%0,%1,%2,%3}, [%4];"
                    : "=r"(b[g][0]), "=r"(b[g][1]), "=r"(b[g][2]), "=r"(b[g][3])
                    : "r"(addr));
            }
#pragma unroll
            for (int mf = 0; mf < 2; mf++)
#pragma unroll
                for (int nn = 0; nn < 4; nn++)
                    mma16816(acc[mf][nn], a[mf][0], a[mf][1], a[mf][2], a[mf][3],
                             b[nn >> 1][nn & 1], b[nn >> 1][(nn & 1) + 2]);
        }
    }
    CP_WAIT0();
}

// GEMM1: h = relu(xs @ W1^T + b1) -> fp16
__global__ __launch_bounds__(512, 2)
void gemm1_kernel(const float* __restrict__ b1) {
    extern __shared__ char smem[];
    float acc[2][4][4] = {};
    gemm_body<FDIM>(g_xs16, g_w1h, acc, smem);

    const int tid  = threadIdx.x;
    const int lane = tid & 31;
    const int warp = tid >> 5;
    const int warp_m = warp >> 2, warp_n = warp & 3;
    const int blockM = blockIdx.y * 128;
    const int blockN = blockIdx.x * 128;

#pragma unroll
    for (int mf = 0; mf < 2; mf++)
#pragma unroll
        for (int nn = 0; nn < 4; nn++) {
            int row = blockM + warp_m * 32 + mf * 16 + (lane >> 2);
            int col = blockN + warp_n * 32 + nn * 8 + (lane & 3) * 2;
            float bb0 = b1[col], bb1 = b1[col + 1];
            __half2 h0 = __floats2half2_rn(fmaxf(acc[mf][nn][0] + bb0, 0.f),
                                           fmaxf(acc[mf][nn][1] + bb1, 0.f));
            __half2 h1 = __floats2half2_rn(fmaxf(acc[mf][nn][2] + bb0, 0.f),
                                           fmaxf(acc[mf][nn][3] + bb1, 0.f));
            *reinterpret_cast<__half2*>(&g_h16[(size_t)row * HDIM + col])       = h0;
            *reinterpret_cast<__half2*>(&g_h16[(size_t)(row + 8) * HDIM + col]) = h1;
        }
}

// GEMM2: y = h @ W2^T + b2 + xs; out[m][inv[n]] = y[m][n]
__global__ __launch_bounds__(512, 2)
void gemm2_kernel(const float* __restrict__ b2, float* __restrict__ out) {
    extern __shared__ char smem[];
    float acc[2][4][4] = {};
    gemm_body<HDIM>(g_h16, g_w2h, acc, smem);

    const int tid  = threadIdx.x;
    const int lane = tid & 31;
    const int warp = tid >> 5;
    const int warp_m = warp >> 2, warp_n = warp & 3;
    const int blockM = blockIdx.y * 128;
    const int blockN = blockIdx.x * 128;

#pragma unroll
    for (int mf = 0; mf < 2; mf++)
#pragma unroll
        for (int nn = 0; nn < 4; nn++) {
            int row = blockM + warp_m * 32 + mf * 16 + (lane >> 2);
            int col = blockN + warp_n * 32 + nn * 8 + (lane & 3) * 2;
            float bb0 = b2[col], bb1 = b2[col + 1];
#pragma unroll
            for (int half = 0; half < 2; half++) {
                int r = row + half * 8;
                size_t base = (size_t)r * FDIM + col;
                float2 xsv = *reinterpret_cast<const float2*>(&g_xs32[base]);
                ushort2 pv = *reinterpret_cast<const ushort2*>(&g_inv[base]);
                float y0 = acc[mf][nn][half * 2 + 0] + bb0 + xsv.x;
                float y1 = acc[mf][nn][half * 2 + 1] + bb1 + xsv.y;
                out[(size_t)r * FDIM + pv.x] = y0;
                out[(size_t)r * FDIM + pv.y] = y1;
            }
        }
}

// ---------------------------------------------------------------------------
// Launch: sequential (overlap regressed twice — all kernels compute-bound).
// ---------------------------------------------------------------------------
extern "C" void kernel_launch(void* const* d_in, const int* in_sizes, int n_in,
                              void* d_out, int out_size) {
    const float* x  = (const float*)d_in[0];
    const float* W1 = (const float*)d_in[1];
    const float* b1 = (const float*)d_in[2];
    const float* W2 = (const float*)d_in[3];
    const float* b2 = (const float*)d_in[4];
    float* out = (float*)d_out;

    cudaFuncSetAttribute(gemm1_kernel, cudaFuncAttributeMaxDynamicSharedMemorySize, SMEM_TOTAL);
    cudaFuncSetAttribute(gemm2_kernel, cudaFuncAttributeMaxDynamicSharedMemorySize, SMEM_TOTAL);

    cvt_weights<<<(2 * HDIM * FDIM / 4) / 256, 256>>>(W1, W2);
    sort_kernel<<<ROWS / 8, 256>>>(x);
    gemm1_kernel<<<dim3(HDIM / 128, ROWS / 128), 512, SMEM_TOTAL>>>(b1);
    gemm2_kernel<<<dim3(FDIM / 128, ROWS / 128), 512, SMEM_TOTAL>>>(b2, out);
}